// round 1
// baseline (speedup 1.0000x reference)
#include <cuda_runtime.h>
#include <math.h>

// Problem constants (fixed by setup_inputs)
#define T_SEQ 2048
#define EMB   2048
#define NH    32
#define NKV   8
#define HD    64
#define NBLK  32      // T_SEQ / 64
#define WIN   256
#define BS    64

// Scratch in device globals (no allocation allowed)
__device__ float g_q[T_SEQ * NH * HD];     // [t][h][d]
__device__ float g_k[T_SEQ * NKV * HD];    // [t][kv][d]
__device__ float g_v[T_SEQ * NKV * HD];
__device__ float g_o[T_SEQ * NH * HD];
__device__ int   g_allow[NBLK * NBLK];

// ---------------------------------------------------------------------------
// Decode rw_allow_blocks robustly: dtype could be bool/int8, int32, or float32.
// Heuristic on first 1024 bytes (safe for every candidate layout):
//   - int32 values {0,1}: bytes at i%4!=0 are all zero.
//   - float32 {0.0,1.0}: bytes at i%4==0 are all zero (LE: 00 00 80 3F).
//   - bool/int8: ~15% of bytes at i%4==0 nonzero.
// ---------------------------------------------------------------------------
__global__ void decode_mask_kernel(const void* p) {
    __shared__ int cnt0, cnt123;
    int tid = threadIdx.x;
    if (tid == 0) { cnt0 = 0; cnt123 = 0; }
    __syncthreads();
    const unsigned char* b = (const unsigned char*)p;
    int l0 = 0, l123 = 0;
    for (int i = tid; i < 1024; i += 256) {
        if (b[i]) { if ((i & 3) == 0) l0++; else l123++; }
    }
    atomicAdd(&cnt0, l0);
    atomicAdd(&cnt123, l123);
    __syncthreads();
    if (cnt123 == 0) {                 // 4-byte int (0/1)
        const int* a = (const int*)p;
        for (int i = tid; i < 1024; i += 256) g_allow[i] = (a[i] != 0);
    } else if (cnt0 == 0) {            // float32 (0.0/1.0)
        const float* a = (const float*)p;
        for (int i = tid; i < 1024; i += 256) g_allow[i] = (a[i] != 0.0f);
    } else {                           // bool / int8
        for (int i = tid; i < 1024; i += 256) g_allow[i] = (b[i] != 0);
    }
}

// ---------------------------------------------------------------------------
// SGEMM: C[M,N] = A[M,K] * B[N,K]^T   (both row-major, all dims % 64 == 0)
// 64x64 tile, BK=16, 256 threads, 4x4 microtile per thread.
// ---------------------------------------------------------------------------
__global__ void sgemm_nt(const float* __restrict__ A, const float* __restrict__ B,
                         float* __restrict__ C, int M, int N, int K) {
    __shared__ float As[16][64];
    __shared__ float Bs[16][64];
    int tid = threadIdx.x;
    int m0 = blockIdx.y * 64;
    int n0 = blockIdx.x * 64;
    int ty = tid >> 4;            // 0..15
    int tx = tid & 15;            // 0..15
    int lr = tid >> 2;            // 0..63 tile row for loads
    int lc = (tid & 3) * 4;       // k offset 0,4,8,12

    float acc[4][4];
#pragma unroll
    for (int i = 0; i < 4; i++)
#pragma unroll
        for (int j = 0; j < 4; j++) acc[i][j] = 0.0f;

    const float* Arow = A + (size_t)(m0 + lr) * K + lc;
    const float* Brow = B + (size_t)(n0 + lr) * K + lc;

    for (int k0 = 0; k0 < K; k0 += 16) {
        float4 a4 = *(const float4*)(Arow + k0);
        float4 b4 = *(const float4*)(Brow + k0);
        __syncthreads();
        As[lc + 0][lr] = a4.x; As[lc + 1][lr] = a4.y;
        As[lc + 2][lr] = a4.z; As[lc + 3][lr] = a4.w;
        Bs[lc + 0][lr] = b4.x; Bs[lc + 1][lr] = b4.y;
        Bs[lc + 2][lr] = b4.z; Bs[lc + 3][lr] = b4.w;
        __syncthreads();
#pragma unroll
        for (int kk = 0; kk < 16; kk++) {
            float4 av = *(const float4*)&As[kk][ty * 4];
            float4 bv = *(const float4*)&Bs[kk][tx * 4];
            float a[4] = {av.x, av.y, av.z, av.w};
            float b[4] = {bv.x, bv.y, bv.z, bv.w};
#pragma unroll
            for (int i = 0; i < 4; i++)
#pragma unroll
                for (int j = 0; j < 4; j++) acc[i][j] += a[i] * b[j];
        }
    }
#pragma unroll
    for (int i = 0; i < 4; i++) {
        float4 cv = make_float4(acc[i][0], acc[i][1], acc[i][2], acc[i][3]);
        *(float4*)&C[(size_t)(m0 + ty * 4 + i) * N + n0 + tx * 4] = cv;
    }
}

// ---------------------------------------------------------------------------
// RoPE applied in-place to q [t][h][64] and k [t][kv][64].
// One thread per (t, head, d<32) pair.
// ---------------------------------------------------------------------------
__global__ void rope_kernel(const float* __restrict__ cosb, const float* __restrict__ sinb) {
    int idx = blockIdx.x * blockDim.x + threadIdx.x;
    const int total = T_SEQ * (NH + NKV) * 32;
    if (idx >= total) return;
    int d = idx & 31;
    int rest = idx >> 5;
    int head = rest % (NH + NKV);
    int t = rest / (NH + NKV);
    float c0 = cosb[t * HD + d];
    float s0 = sinb[t * HD + d];
    float c1 = cosb[t * HD + d + 32];
    float s1 = sinb[t * HD + d + 32];
    float* base = (head < NH) ? (g_q + ((size_t)t * NH + head) * HD)
                              : (g_k + ((size_t)t * NKV + (head - NH)) * HD);
    float x0 = base[d];
    float x1 = base[d + 32];
    base[d]      = x0 * c0 - x1 * s0;
    base[d + 32] = x1 * c1 + x0 * s1;
}

// ---------------------------------------------------------------------------
// Flash-style attention. One block per (head, q-block of 64 rows).
// Thread r owns q-row r: q & accumulator in registers, K/V tile in smem
// (reads are warp-broadcast), scores staged in smem [j][r] (conflict-free).
// Mask: allow_block || (kj < 256) || (kj <= qi && kj >= qi-255).
// ---------------------------------------------------------------------------
__global__ void attn_kernel() {
    int h  = blockIdx.x;   // 0..31
    int qb = blockIdx.y;   // 0..31
    int r  = threadIdx.x;  // 0..63
    int kv = h >> 2;       // n_rep = 4
    int qi = qb * 64 + r;

    __shared__ float Kt[64][64];
    __shared__ float Vt[64][64];
    __shared__ float S[64][64];

    float qreg[64];
    const float* qrow = g_q + ((size_t)qi * NH + h) * HD;
#pragma unroll
    for (int d = 0; d < 64; d++) qreg[d] = qrow[d] * 0.125f;  // fold D^-0.5

    float m = -1e30f, l = 0.0f;
    float acc[64];
#pragma unroll
    for (int d = 0; d < 64; d++) acc[d] = 0.0f;

    for (int kb = 0; kb < NBLK; kb++) {
        int ba = g_allow[qb * NBLK + kb];
        bool win_possible = (kb < 4) || (kb <= qb && kb + 4 >= qb);
        if (!ba && !win_possible) continue;   // block-uniform

        __syncthreads();
        for (int idx = r; idx < 64 * 64; idx += 64) {
            int j = idx >> 6, d = idx & 63;
            size_t goff = ((size_t)(kb * 64 + j) * NKV + kv) * HD + d;
            Kt[j][d] = g_k[goff];
            Vt[j][d] = g_v[goff];
        }
        __syncthreads();

        float mb = -1e30f;
        for (int j = 0; j < 64; j++) {
            int kj = kb * 64 + j;
            bool ok = ba || (kj < WIN) || (kj <= qi && kj + (WIN - 1) >= qi);
            float s = -1e30f;
            if (ok) {
                s = 0.0f;
#pragma unroll
                for (int d = 0; d < 64; d++) s += qreg[d] * Kt[j][d];
            }
            S[j][r] = s;
            mb = fmaxf(mb, s);
        }
        if (mb > -5e29f) {
            float mnew = fmaxf(m, mb);
            float sc = __expf(m - mnew);
            m = mnew;
            l *= sc;
#pragma unroll
            for (int d = 0; d < 64; d++) acc[d] *= sc;
            for (int j = 0; j < 64; j++) {
                float p = __expf(S[j][r] - m);  // masked rows -> 0
                l += p;
#pragma unroll
                for (int d = 0; d < 64; d++) acc[d] += p * Vt[j][d];
            }
        }
    }
    float inv = 1.0f / l;   // l > 0 always (first 256 keys always allowed)
    float* orow = g_o + ((size_t)qi * NH + h) * HD;
#pragma unroll
    for (int d = 0; d < 64; d++) orow[d] = acc[d] * inv;
}

// ---------------------------------------------------------------------------
extern "C" void kernel_launch(void* const* d_in, const int* in_sizes, int n_in,
                              void* d_out, int out_size) {
    const float* hs   = (const float*)d_in[0];  // [1,2048,2048]
    const float* cosb = (const float*)d_in[1];  // [1,2048,64]
    const float* sinb = (const float*)d_in[2];
    const float* Wq   = (const float*)d_in[3];  // [2048,2048]
    const float* Wk   = (const float*)d_in[4];  // [512,2048]
    const float* Wv   = (const float*)d_in[5];
    const float* Wo   = (const float*)d_in[6];  // [2048,2048]
    const void*  allow = d_in[7];               // [1,32,32] bool-ish
    float* out = (float*)d_out;

    float *qp, *kp, *vp, *op;
    cudaGetSymbolAddress((void**)&qp, g_q);
    cudaGetSymbolAddress((void**)&kp, g_k);
    cudaGetSymbolAddress((void**)&vp, g_v);
    cudaGetSymbolAddress((void**)&op, g_o);

    decode_mask_kernel<<<1, 256>>>(allow);

    // QKV projections
    sgemm_nt<<<dim3(EMB / 64, T_SEQ / 64), 256>>>(hs, Wq, qp, T_SEQ, NH * HD, EMB);
    sgemm_nt<<<dim3((NKV * HD) / 64, T_SEQ / 64), 256>>>(hs, Wk, kp, T_SEQ, NKV * HD, EMB);
    sgemm_nt<<<dim3((NKV * HD) / 64, T_SEQ / 64), 256>>>(hs, Wv, vp, T_SEQ, NKV * HD, EMB);

    // RoPE on q and k
    {
        int total = T_SEQ * (NH + NKV) * 32;
        rope_kernel<<<(total + 255) / 256, 256>>>(cosb, sinb);
    }

    // Masked flash attention
    attn_kernel<<<dim3(NH, NBLK), 64>>>();

    // Output projection
    sgemm_nt<<<dim3(EMB / 64, T_SEQ / 64), 256>>>(op, Wo, out, T_SEQ, EMB, EMB);
}

// round 2
// speedup vs baseline: 1.5085x; 1.5085x over previous
#include <cuda_runtime.h>
#include <cuda_bf16.h>
#include <math.h>
#include <stdint.h>

// Problem constants (fixed by setup_inputs)
#define T_SEQ 2048
#define EMB   2048
#define NH    32
#define NKV   8
#define HD    64
#define NBLK  32      // T_SEQ / 64
#define WIN   256

// Scratch in device globals (no allocation allowed)
__device__ float g_q[T_SEQ * NH * HD];     // [t][h][d]
__device__ float g_k[T_SEQ * NKV * HD];    // [t][kv][d]
__device__ float g_v[T_SEQ * NKV * HD];
__device__ float g_o[T_SEQ * NH * HD];
__device__ int   g_allow[NBLK * NBLK];

// ---------------------------------------------------------------------------
// Decode rw_allow_blocks robustly (bool/int8 vs int32 vs float32).
// ---------------------------------------------------------------------------
__global__ void decode_mask_kernel(const void* p) {
    __shared__ int cnt0, cnt123;
    int tid = threadIdx.x;
    if (tid == 0) { cnt0 = 0; cnt123 = 0; }
    __syncthreads();
    const unsigned char* b = (const unsigned char*)p;
    int l0 = 0, l123 = 0;
    for (int i = tid; i < 1024; i += 256) {
        if (b[i]) { if ((i & 3) == 0) l0++; else l123++; }
    }
    atomicAdd(&cnt0, l0);
    atomicAdd(&cnt123, l123);
    __syncthreads();
    if (cnt123 == 0) {
        const int* a = (const int*)p;
        for (int i = tid; i < 1024; i += 256) g_allow[i] = (a[i] != 0);
    } else if (cnt0 == 0) {
        const float* a = (const float*)p;
        for (int i = tid; i < 1024; i += 256) g_allow[i] = (a[i] != 0.0f);
    } else {
        for (int i = tid; i < 1024; i += 256) g_allow[i] = (b[i] != 0);
    }
}

// ---------------------------------------------------------------------------
// Tensor-core GEMM: C[M,N] = A[M,K] * B[N,K]^T, fp32 in/out.
// bf16 3-term split (hi/lo) on tensor cores: error ~2^-18 per product.
// Block tile 128x128, BK=32, 8 warps, warp tile 64x32 (m16n8k16 atoms).
// ---------------------------------------------------------------------------
#define MMA_BF16(d, a0, a1, a2, a3, b0, b1)                                   \
    asm volatile(                                                             \
        "mma.sync.aligned.m16n8k16.row.col.f32.bf16.bf16.f32 "                \
        "{%0,%1,%2,%3}, {%4,%5,%6,%7}, {%8,%9}, {%0,%1,%2,%3};"               \
        : "+f"(d[0]), "+f"(d[1]), "+f"(d[2]), "+f"(d[3])                      \
        : "r"(a0), "r"(a1), "r"(a2), "r"(a3), "r"(b0), "r"(b1))

__device__ __forceinline__ uint32_t pack_bf16x2(float f0, float f1) {
    __nv_bfloat162 h = __floats2bfloat162_rn(f0, f1);
    return *reinterpret_cast<uint32_t*>(&h);
}

#define SMSTRIDE 40   // halves per row: banks (20r + c) mod 32 all distinct

__global__ __launch_bounds__(256, 2)
void sgemm_tc(const float* __restrict__ A, const float* __restrict__ B,
              float* __restrict__ C, int M, int N, int K) {
    __shared__ __nv_bfloat16 sAh[128][SMSTRIDE];
    __shared__ __nv_bfloat16 sAl[128][SMSTRIDE];
    __shared__ __nv_bfloat16 sBh[128][SMSTRIDE];
    __shared__ __nv_bfloat16 sBl[128][SMSTRIDE];

    int tid  = threadIdx.x;
    int warp = tid >> 5;
    int lane = tid & 31;
    int wm = warp & 1;        // 2 m-slots of 64
    int wn = warp >> 1;       // 4 n-slots of 32
    int m0 = blockIdx.y * 128;
    int n0 = blockIdx.x * 128;

    float acc[4][4][4];
#pragma unroll
    for (int i = 0; i < 4; i++)
#pragma unroll
        for (int j = 0; j < 4; j++)
#pragma unroll
            for (int e = 0; e < 4; e++) acc[i][j][e] = 0.0f;

    int lr = tid >> 3;              // 0..31
    int lk = (tid & 7) * 4;         // k offset within BK=32

    int qr = lane >> 2;             // lane/4
    int qc = (lane & 3) * 2;        // fragment k/col offset

    for (int k0 = 0; k0 < K; k0 += 32) {
        // ---- stage tiles: fp32 -> bf16 hi/lo ----
#pragma unroll
        for (int rr = 0; rr < 4; rr++) {
            int row = lr + rr * 32;
            float4 a = *(const float4*)(A + (size_t)(m0 + row) * K + k0 + lk);
            float4 b = *(const float4*)(B + (size_t)(n0 + row) * K + k0 + lk);

            __nv_bfloat16 ah0 = __float2bfloat16(a.x), ah1 = __float2bfloat16(a.y);
            __nv_bfloat16 ah2 = __float2bfloat16(a.z), ah3 = __float2bfloat16(a.w);
            float al0 = a.x - __bfloat162float(ah0), al1 = a.y - __bfloat162float(ah1);
            float al2 = a.z - __bfloat162float(ah2), al3 = a.w - __bfloat162float(ah3);
            uint2 hv, lv;
            hv.x = pack_bf16x2(__bfloat162float(ah0), __bfloat162float(ah1));
            hv.y = pack_bf16x2(__bfloat162float(ah2), __bfloat162float(ah3));
            lv.x = pack_bf16x2(al0, al1);
            lv.y = pack_bf16x2(al2, al3);
            *(uint2*)&sAh[row][lk] = hv;
            *(uint2*)&sAl[row][lk] = lv;

            __nv_bfloat16 bh0 = __float2bfloat16(b.x), bh1 = __float2bfloat16(b.y);
            __nv_bfloat16 bh2 = __float2bfloat16(b.z), bh3 = __float2bfloat16(b.w);
            float bl0 = b.x - __bfloat162float(bh0), bl1 = b.y - __bfloat162float(bh1);
            float bl2 = b.z - __bfloat162float(bh2), bl3 = b.w - __bfloat162float(bh3);
            hv.x = pack_bf16x2(__bfloat162float(bh0), __bfloat162float(bh1));
            hv.y = pack_bf16x2(__bfloat162float(bh2), __bfloat162float(bh3));
            lv.x = pack_bf16x2(bl0, bl1);
            lv.y = pack_bf16x2(bl2, bl3);
            *(uint2*)&sBh[row][lk] = hv;
            *(uint2*)&sBl[row][lk] = lv;
        }
        __syncthreads();

        // ---- compute ----
#pragma unroll
        for (int k1 = 0; k1 < 32; k1 += 16) {
            uint32_t ah[4][4], al[4][4];
#pragma unroll
            for (int mi = 0; mi < 4; mi++) {
                int r = wm * 64 + mi * 16 + qr;
                int c = k1 + qc;
                ah[mi][0] = *(const uint32_t*)&sAh[r][c];
                ah[mi][1] = *(const uint32_t*)&sAh[r + 8][c];
                ah[mi][2] = *(const uint32_t*)&sAh[r][c + 8];
                ah[mi][3] = *(const uint32_t*)&sAh[r + 8][c + 8];
                al[mi][0] = *(const uint32_t*)&sAl[r][c];
                al[mi][1] = *(const uint32_t*)&sAl[r + 8][c];
                al[mi][2] = *(const uint32_t*)&sAl[r][c + 8];
                al[mi][3] = *(const uint32_t*)&sAl[r + 8][c + 8];
            }
#pragma unroll
            for (int ni = 0; ni < 4; ni++) {
                int n = wn * 32 + ni * 8 + qr;
                int c = k1 + qc;
                uint32_t bh0 = *(const uint32_t*)&sBh[n][c];
                uint32_t bh1 = *(const uint32_t*)&sBh[n][c + 8];
                uint32_t bl0 = *(const uint32_t*)&sBl[n][c];
                uint32_t bl1 = *(const uint32_t*)&sBl[n][c + 8];
#pragma unroll
                for (int mi = 0; mi < 4; mi++) {
                    MMA_BF16(acc[mi][ni], ah[mi][0], ah[mi][1], ah[mi][2], ah[mi][3], bh0, bh1);
                    MMA_BF16(acc[mi][ni], ah[mi][0], ah[mi][1], ah[mi][2], ah[mi][3], bl0, bl1);
                    MMA_BF16(acc[mi][ni], al[mi][0], al[mi][1], al[mi][2], al[mi][3], bh0, bh1);
                }
            }
        }
        __syncthreads();
    }

    // ---- epilogue ----
#pragma unroll
    for (int mi = 0; mi < 4; mi++) {
#pragma unroll
        for (int ni = 0; ni < 4; ni++) {
            int r = m0 + wm * 64 + mi * 16 + qr;
            int cidx = n0 + wn * 32 + ni * 8 + qc;
            float2 v0 = make_float2(acc[mi][ni][0], acc[mi][ni][1]);
            float2 v1 = make_float2(acc[mi][ni][2], acc[mi][ni][3]);
            *(float2*)&C[(size_t)r * N + cidx] = v0;
            *(float2*)&C[(size_t)(r + 8) * N + cidx] = v1;
        }
    }
}

// ---------------------------------------------------------------------------
// RoPE applied in-place to q and k.
// ---------------------------------------------------------------------------
__global__ void rope_kernel(const float* __restrict__ cosb, const float* __restrict__ sinb) {
    int idx = blockIdx.x * blockDim.x + threadIdx.x;
    const int total = T_SEQ * (NH + NKV) * 32;
    if (idx >= total) return;
    int d = idx & 31;
    int rest = idx >> 5;
    int head = rest % (NH + NKV);
    int t = rest / (NH + NKV);
    float c0 = cosb[t * HD + d];
    float s0 = sinb[t * HD + d];
    float c1 = cosb[t * HD + d + 32];
    float s1 = sinb[t * HD + d + 32];
    float* base = (head < NH) ? (g_q + ((size_t)t * NH + head) * HD)
                              : (g_k + ((size_t)t * NKV + (head - NH)) * HD);
    float x0 = base[d];
    float x1 = base[d + 32];
    base[d]      = x0 * c0 - x1 * s0;
    base[d + 32] = x1 * c1 + x0 * s1;
}

// ---------------------------------------------------------------------------
// Flash-style masked attention (unchanged from R0).
// ---------------------------------------------------------------------------
__global__ void attn_kernel() {
    int h  = blockIdx.x;
    int qb = blockIdx.y;
    int r  = threadIdx.x;
    int kv = h >> 2;
    int qi = qb * 64 + r;

    __shared__ float Kt[64][64];
    __shared__ float Vt[64][64];
    __shared__ float S[64][64];

    float qreg[64];
    const float* qrow = g_q + ((size_t)qi * NH + h) * HD;
#pragma unroll
    for (int d = 0; d < 64; d++) qreg[d] = qrow[d] * 0.125f;

    float m = -1e30f, l = 0.0f;
    float acc[64];
#pragma unroll
    for (int d = 0; d < 64; d++) acc[d] = 0.0f;

    for (int kb = 0; kb < NBLK; kb++) {
        int ba = g_allow[qb * NBLK + kb];
        bool win_possible = (kb < 4) || (kb <= qb && kb + 4 >= qb);
        if (!ba && !win_possible) continue;

        __syncthreads();
        for (int idx = r; idx < 64 * 64; idx += 64) {
            int j = idx >> 6, d = idx & 63;
            size_t goff = ((size_t)(kb * 64 + j) * NKV + kv) * HD + d;
            Kt[j][d] = g_k[goff];
            Vt[j][d] = g_v[goff];
        }
        __syncthreads();

        float mb = -1e30f;
        for (int j = 0; j < 64; j++) {
            int kj = kb * 64 + j;
            bool ok = ba || (kj < WIN) || (kj <= qi && kj + (WIN - 1) >= qi);
            float s = -1e30f;
            if (ok) {
                s = 0.0f;
#pragma unroll
                for (int d = 0; d < 64; d++) s += qreg[d] * Kt[j][d];
            }
            S[j][r] = s;
            mb = fmaxf(mb, s);
        }
        if (mb > -5e29f) {
            float mnew = fmaxf(m, mb);
            float sc = __expf(m - mnew);
            m = mnew;
            l *= sc;
#pragma unroll
            for (int d = 0; d < 64; d++) acc[d] *= sc;
            for (int j = 0; j < 64; j++) {
                float p = __expf(S[j][r] - m);
                l += p;
#pragma unroll
                for (int d = 0; d < 64; d++) acc[d] += p * Vt[j][d];
            }
        }
    }
    float inv = 1.0f / l;
    float* orow = g_o + ((size_t)qi * NH + h) * HD;
#pragma unroll
    for (int d = 0; d < 64; d++) orow[d] = acc[d] * inv;
}

// ---------------------------------------------------------------------------
extern "C" void kernel_launch(void* const* d_in, const int* in_sizes, int n_in,
                              void* d_out, int out_size) {
    const float* hs   = (const float*)d_in[0];
    const float* cosb = (const float*)d_in[1];
    const float* sinb = (const float*)d_in[2];
    const float* Wq   = (const float*)d_in[3];
    const float* Wk   = (const float*)d_in[4];
    const float* Wv   = (const float*)d_in[5];
    const float* Wo   = (const float*)d_in[6];
    const void*  allow = d_in[7];
    float* out = (float*)d_out;

    float *qp, *kp, *vp, *op;
    cudaGetSymbolAddress((void**)&qp, g_q);
    cudaGetSymbolAddress((void**)&kp, g_k);
    cudaGetSymbolAddress((void**)&vp, g_v);
    cudaGetSymbolAddress((void**)&op, g_o);

    decode_mask_kernel<<<1, 256>>>(allow);

    // QKV projections (tensor cores, bf16 3-term)
    sgemm_tc<<<dim3(EMB / 128, T_SEQ / 128), 256>>>(hs, Wq, qp, T_SEQ, NH * HD, EMB);
    sgemm_tc<<<dim3((NKV * HD) / 128, T_SEQ / 128), 256>>>(hs, Wk, kp, T_SEQ, NKV * HD, EMB);
    sgemm_tc<<<dim3((NKV * HD) / 128, T_SEQ / 128), 256>>>(hs, Wv, vp, T_SEQ, NKV * HD, EMB);

    // RoPE
    {
        int total = T_SEQ * (NH + NKV) * 32;
        rope_kernel<<<(total + 255) / 256, 256>>>(cosb, sinb);
    }

    // Masked flash attention
    attn_kernel<<<dim3(NH, NBLK), 64>>>();

    // Output projection
    sgemm_tc<<<dim3(EMB / 128, T_SEQ / 128), 256>>>(op, Wo, out, T_SEQ, EMB, EMB);
}